// round 5
// baseline (speedup 1.0000x reference)
#include <cuda_runtime.h>
#include <math.h>

#define NN 256
#define HH 256
#define DDE 64
#define NHD 4
#define CHUNK 32
#define NCHUNK 8
#define GH_STRIDE 256

typedef unsigned long long ull;

__device__ __forceinline__ ull pk2(float lo, float hi) {
    ull r; asm("mov.b64 %0,{%1,%2};" : "=l"(r) : "f"(lo), "f"(hi)); return r;
}
__device__ __forceinline__ float2 upk2(ull v) {
    float lo, hi; asm("mov.b64 {%0,%1},%2;" : "=f"(lo), "=f"(hi) : "l"(v));
    float2 f; f.x = lo; f.y = hi; return f;
}
__device__ __forceinline__ ull fma2_(ull a, ull b, ull c) {
    ull d; asm("fma.rn.f32x2 %0,%1,%2,%3;" : "=l"(d) : "l"(a), "l"(b), "l"(c)); return d;
}
__device__ __forceinline__ ull mul2_(ull a, ull b) {
    ull d; asm("mul.rn.f32x2 %0,%1,%2;" : "=l"(d) : "l"(a), "l"(b)); return d;
}
__device__ __forceinline__ float tanh_ap(float x) {
    float y; asm("tanh.approx.f32 %0,%1;" : "=f"(y) : "f"(x)); return y;
}

// ---------------- device scratch ----------------
__device__ float g_tTj[NN * HH];   // tanh(ahs[j,h])
__device__ float g_PT[DDE * NN];
__device__ float g_C [NN * DDE];
__device__ float g_u [NHD * HH];
__device__ float g_v [NHD * HH];
__device__ float g_msm[NN * NHD * HH];

// ---------------- prep kernels ----------------
__global__ void prepA(const float* __restrict__ ahs, const float* __restrict__ goal,
                      const float* __restrict__ action, const float* __restrict__ Wd,
                      const float* __restrict__ bd) {
    const int j = blockIdx.x, t = threadIdx.x;
    g_tTj[j * HH + t] = tanhf(ahs[j * HH + t]);
    if (t < DDE) {
        const float a0 = action[j * 2 + 0], a1 = action[j * 2 + 1];
        const float go0 = goal[j * 2 + 0], go1 = goal[j * 2 + 1];
        g_PT[t * NN + j] = a0 * Wd[4 * DDE + t] + a1 * Wd[5 * DDE + t]
                         + go0 * Wd[6 * DDE + t] + go1 * Wd[7 * DDE + t];
        g_C[j * DDE + t] = a0 * Wd[0 * DDE + t] + a1 * Wd[1 * DDE + t]
                         + go0 * Wd[2 * DDE + t] + go1 * Wd[3 * DDE + t] + bd[t];
    }
}

__global__ void prepB(const float* __restrict__ w, const float* __restrict__ a) {
    const int warp = (blockIdx.x * blockDim.x + threadIdx.x) >> 5;  // z*256+h
    const int lane = threadIdx.x & 31;
    const float* row = w + warp * HH;
    float su = 0.f, sv = 0.f;
    #pragma unroll
    for (int f = lane; f < HH; f += 32) {
        const float wv = row[f];
        su = fmaf(wv, a[f], su);
        sv = fmaf(wv, a[HH + f], sv);
    }
    #pragma unroll
    for (int o = 16; o; o >>= 1) {
        su += __shfl_down_sync(0xffffffffu, su, o);
        sv += __shfl_down_sync(0xffffffffu, sv, o);
    }
    if (lane == 0) { g_u[warp] = su; g_v[warp] = sv; }
}

// ---------------- main fused kernel ----------------
// smem floats: Wg_s 16384 | gh/qs_dup union 8192 | esh 128 | psh 128 | bc 16 | cvec 16
#define SM_FLOATS (16384 + CHUNK * GH_STRIDE + 128 + 128 + 16 + 16)
#define SM_BYTES  (SM_FLOATS * 4)

__global__ void __launch_bounds__(256, 2) mainK(
    const float* __restrict__ ahs, const float* __restrict__ ghs,
    const float* __restrict__ Wg, const float* __restrict__ bg)
{
    extern __shared__ float sm[];
    float* Wg_s = sm;                       // [d][h]          16384
    float* gh   = Wg_s + DDE * HH;          // [jl][h] s=256   8192  (qs_dup aliased here)
    float* qs   = gh;                       // [d][2j dup]     4096  (alias, disjoint lifetime)
    float* esh  = gh + CHUNK * GH_STRIDE;   // [z][jl]         128
    float* psh  = esh + 128;                // [jl][z]         128
    float* bc   = psh + 128;                // 16
    float* cvec = bc + 16;                  // c1[0..3], s0[4..7]

    const int i    = blockIdx.x;
    const int tid  = threadIdx.x;
    const int lane = tid & 31;
    const int warp = tid >> 5;     // jg: owns j = warp*4 .. +3
    // thread owns h = lane*8 .. +7

    for (int k = tid; k < DDE * HH; k += 256) Wg_s[k] = Wg[k];

    // prologue dots: warp (z*2+sel): c1/s0 for this row
    {
        const int z = warp >> 1;
        const float* src = (warp & 1) ? (g_v + z * HH) : (g_u + z * HH);
        float s = 0.f;
        #pragma unroll
        for (int h = lane; h < HH; h += 32) s = fmaf(ahs[i * HH + h], src[h], s);
        #pragma unroll
        for (int o = 16; o; o >>= 1) s += __shfl_xor_sync(0xffffffffu, s, o);
        if (lane == 0) cvec[(warp & 1) * 4 + z] = s;
    }

    // per-thread v values at this thread's 8 h, 4 heads (32 regs)
    float vz0[8], vz1[8], vz2[8], vz3[8];
    {
        #pragma unroll
        for (int p = 0; p < 2; p++) {
            const float4 a0 = *(const float4*)&g_v[0 * HH + lane * 8 + p * 4];
            const float4 a1 = *(const float4*)&g_v[1 * HH + lane * 8 + p * 4];
            const float4 a2 = *(const float4*)&g_v[2 * HH + lane * 8 + p * 4];
            const float4 a3 = *(const float4*)&g_v[3 * HH + lane * 8 + p * 4];
            vz0[p*4+0]=a0.x; vz0[p*4+1]=a0.y; vz0[p*4+2]=a0.z; vz0[p*4+3]=a0.w;
            vz1[p*4+0]=a1.x; vz1[p*4+1]=a1.y; vz1[p*4+2]=a1.z; vz1[p*4+3]=a1.w;
            vz2[p*4+0]=a2.x; vz2[p*4+1]=a2.y; vz2[p*4+2]=a2.z; vz2[p*4+3]=a2.w;
            vz3[p*4+0]=a3.x; vz3[p*4+1]=a3.y; vz3[p*4+2]=a3.z; vz3[p*4+3]=a3.w;
        }
    }
    // gate bias: natural h-pairs (4 ull)
    ull bgp[4];
    {
        const ulonglong2 b0 = *(const ulonglong2*)&bg[lane * 8];
        const ulonglong2 b1 = *(const ulonglong2*)&bg[lane * 8 + 4];
        bgp[0] = b0.x; bgp[1] = b0.y; bgp[2] = b1.x; bgp[3] = b1.y;
    }

    const float ahs_i = ahs[i * HH + tid];
    __syncthreads();

    // online-softmax state (replicated)
    float runmax0, runmax1, runmax2, runmax3;
    float denom0 = 1.f, denom1 = 1.f, denom2 = 1.f, denom3 = 1.f;
    {
        const float s0v = cvec[0] + cvec[4], s1v = cvec[1] + cvec[5];
        const float s2v = cvec[2] + cvec[6], s3v = cvec[3] + cvec[7];
        runmax0 = (s0v > 0.f) ? s0v : 0.2f * s0v;
        runmax1 = (s1v > 0.f) ? s1v : 0.2f * s1v;
        runmax2 = (s2v > 0.f) ? s2v : 0.2f * s2v;
        runmax3 = (s3v > 0.f) ? s3v : 0.2f * s3v;
    }
    ull mA = pk2(ahs_i, ahs_i), mB = mA;   // (m0,m1),(m2,m3)

    for (int c = 0; c < NCHUNK; c++) {
        const int j0 = c * CHUNK;

        // qs_dup[d][2*jj] = qs_dup[d][2*jj+1] = relu(C[i,d] + PT[d, j0+jj])
        for (int idx = tid; idx < DDE * CHUNK; idx += 256) {
            const int d = idx >> 5, jj = idx & 31;
            const float val = fmaxf(g_C[i * DDE + d] + g_PT[d * NN + j0 + jj], 0.f);
            ((ull*)qs)[d * 32 + jj] = pk2(val, val);
        }
        __syncthreads();

        // ---- gate GEMM: 4 j x 8 h (4 h-pairs) per thread, zero-pack FFMA2 ----
        ull acc[4][4];   // [jj][hp]
        #pragma unroll
        for (int jj = 0; jj < 4; jj++) {
            acc[jj][0] = bgp[0]; acc[jj][1] = bgp[1];
            acc[jj][2] = bgp[2]; acc[jj][3] = bgp[3];
        }
        #pragma unroll 2
        for (int d = 0; d < DDE; d++) {
            // q-dup: warp-uniform broadcast loads
            const ulonglong2 qA = *(const ulonglong2*)&qs[d * 64 + warp * 8];
            const ulonglong2 qB = *(const ulonglong2*)&qs[d * 64 + warp * 8 + 4];
            // w: natural h-pairs
            const ulonglong2 wA = *(const ulonglong2*)&Wg_s[d * HH + lane * 8];
            const ulonglong2 wB = *(const ulonglong2*)&Wg_s[d * HH + lane * 8 + 4];
            acc[0][0] = fma2_(qA.x, wA.x, acc[0][0]);
            acc[0][1] = fma2_(qA.x, wA.y, acc[0][1]);
            acc[0][2] = fma2_(qA.x, wB.x, acc[0][2]);
            acc[0][3] = fma2_(qA.x, wB.y, acc[0][3]);
            acc[1][0] = fma2_(qA.y, wA.x, acc[1][0]);
            acc[1][1] = fma2_(qA.y, wA.y, acc[1][1]);
            acc[1][2] = fma2_(qA.y, wB.x, acc[1][2]);
            acc[1][3] = fma2_(qA.y, wB.y, acc[1][3]);
            acc[2][0] = fma2_(qB.x, wA.x, acc[2][0]);
            acc[2][1] = fma2_(qB.x, wA.y, acc[2][1]);
            acc[2][2] = fma2_(qB.x, wB.x, acc[2][2]);
            acc[2][3] = fma2_(qB.x, wB.y, acc[2][3]);
            acc[3][0] = fma2_(qB.y, wA.x, acc[3][0]);
            acc[3][1] = fma2_(qB.y, wA.y, acc[3][1]);
            acc[3][2] = fma2_(qB.y, wB.x, acc[3][2]);
            acc[3][3] = fma2_(qB.y, wB.y, acc[3][3]);
        }
        __syncthreads();   // everyone done reading qs before gh overwrites the alias

        // ---- epilogue: sigmoid*tanh (diag override), store gh, fused scores ----
        #pragma unroll
        for (int jj = 0; jj < 4; jj++) {
            const int jloc = warp * 4 + jj;
            const int j = j0 + jloc;
            float xs[8];
            #pragma unroll
            for (int hp = 0; hp < 4; hp++) {
                const float2 f = upk2(acc[jj][hp]);
                xs[hp * 2] = f.x; xs[hp * 2 + 1] = f.y;
            }
            float gv[8];
            if (j == i) {
                const float4 ga = *(const float4*)&ghs[i * HH + lane * 8];
                const float4 gb = *(const float4*)&ghs[i * HH + lane * 8 + 4];
                gv[0]=ga.x; gv[1]=ga.y; gv[2]=ga.z; gv[3]=ga.w;
                gv[4]=gb.x; gv[5]=gb.y; gv[6]=gb.z; gv[7]=gb.w;
            } else {
                const float4 ta = *(const float4*)&g_tTj[j * HH + lane * 8];
                const float4 tb = *(const float4*)&g_tTj[j * HH + lane * 8 + 4];
                const float t8[8] = {ta.x, ta.y, ta.z, ta.w, tb.x, tb.y, tb.z, tb.w};
                #pragma unroll
                for (int h = 0; h < 8; h++) {
                    const float sg = fmaf(tanh_ap(0.5f * xs[h]), 0.5f, 0.5f);
                    gv[h] = sg * t8[h];
                }
            }
            *(float4*)&gh[jloc * GH_STRIDE + lane * 8]     = make_float4(gv[0], gv[1], gv[2], gv[3]);
            *(float4*)&gh[jloc * GH_STRIDE + lane * 8 + 4] = make_float4(gv[4], gv[5], gv[6], gv[7]);

            float p0 = 0.f, p1 = 0.f, p2 = 0.f, p3 = 0.f;
            #pragma unroll
            for (int h = 0; h < 8; h++) {
                p0 = fmaf(gv[h], vz0[h], p0);
                p1 = fmaf(gv[h], vz1[h], p1);
                p2 = fmaf(gv[h], vz2[h], p2);
                p3 = fmaf(gv[h], vz3[h], p3);
            }
            #pragma unroll
            for (int o = 16; o; o >>= 1) {
                p0 += __shfl_xor_sync(0xffffffffu, p0, o);
                p1 += __shfl_xor_sync(0xffffffffu, p1, o);
                p2 += __shfl_xor_sync(0xffffffffu, p2, o);
                p3 += __shfl_xor_sync(0xffffffffu, p3, o);
            }
            if (lane < 4) {   // full-warp reduction covered all 256 h
                const float pv = (lane == 0) ? p0 : (lane == 1) ? p1 : (lane == 2) ? p2 : p3;
                const float sc = cvec[lane] + pv;
                esh[lane * CHUNK + jloc] = (sc > 0.f) ? sc : 0.2f * sc;
            }
        }
        __syncthreads();

        // ---- chunk softmax: warp z in {0..3} ----
        if (warp < 4) {
            const float rmz = (warp == 0) ? runmax0 : (warp == 1) ? runmax1
                            : (warp == 2) ? runmax2 : runmax3;
            const float e = esh[warp * CHUNK + lane];
            float mx = e;
            #pragma unroll
            for (int o = 16; o; o >>= 1) mx = fmaxf(mx, __shfl_xor_sync(0xffffffffu, mx, o));
            const float nm = fmaxf(rmz, mx);
            const float p = __expf(e - nm);
            psh[lane * 4 + warp] = p;
            float ps = p;
            #pragma unroll
            for (int o = 16; o; o >>= 1) ps += __shfl_xor_sync(0xffffffffu, ps, o);
            if (lane == 0) { bc[warp] = mx; bc[4 + warp] = ps; }
        }
        __syncthreads();

        // ---- merge running state, accumulate m for h = tid ----
        {
            const float nm0 = fmaxf(runmax0, bc[0]);
            const float nm1 = fmaxf(runmax1, bc[1]);
            const float nm2 = fmaxf(runmax2, bc[2]);
            const float nm3 = fmaxf(runmax3, bc[3]);
            const float s0 = __expf(runmax0 - nm0), s1 = __expf(runmax1 - nm1);
            const float s2 = __expf(runmax2 - nm2), s3 = __expf(runmax3 - nm3);
            denom0 = denom0 * s0 + bc[4]; denom1 = denom1 * s1 + bc[5];
            denom2 = denom2 * s2 + bc[6]; denom3 = denom3 * s3 + bc[7];
            runmax0 = nm0; runmax1 = nm1; runmax2 = nm2; runmax3 = nm3;
            mA = mul2_(mA, pk2(s0, s1));
            mB = mul2_(mB, pk2(s2, s3));
        }
        #pragma unroll 4
        for (int jj = 0; jj < CHUNK; jj++) {
            const float ghv = gh[jj * GH_STRIDE + tid];
            const ulonglong2 pp = *(const ulonglong2*)&psh[jj * 4];
            const ull gd = pk2(ghv, ghv);
            mA = fma2_(pp.x, gd, mA);
            mB = fma2_(pp.y, gd, mB);
        }
        __syncthreads();   // gh (alias qs) safe to overwrite next chunk
    }

    // write normalized m: g_msm[i][z*256 + h]
    {
        const float2 fA = upk2(mA), fB = upk2(mB);
        g_msm[i * (NHD * HH) + 0 * HH + tid] = fA.x / denom0;
        g_msm[i * (NHD * HH) + 1 * HH + tid] = fA.y / denom1;
        g_msm[i * (NHD * HH) + 2 * HH + tid] = fB.x / denom2;
        g_msm[i * (NHD * HH) + 3 * HH + tid] = fB.y / denom3;
    }
}

// ---------------- projection kernel (R3 scalar version) ----------------
__global__ void __launch_bounds__(256) projK(const float* __restrict__ w,
                                             const float* __restrict__ bias,
                                             float* __restrict__ out) {
    __shared__ float msm_s[8192];   // [k][n], n contiguous (8)
    __shared__ float sacc[2048];    // [kw][n][fl]
    const int tid = threadIdx.x;
    const int f0 = (blockIdx.x & 7) * 32;
    const int n0 = (blockIdx.x >> 3) * 8;

    for (int idx = tid; idx < 8192; idx += 256) {
        const int k = idx >> 3, n = idx & 7;
        msm_s[idx] = g_msm[(n0 + n) * 1024 + k];
    }
    __syncthreads();

    const int fl = tid & 31, kw = tid >> 5;
    float acc[8] = {0.f, 0.f, 0.f, 0.f, 0.f, 0.f, 0.f, 0.f};
    const float* wp = w + f0 + fl;
    const int kbeg = kw * 128;
    #pragma unroll 4
    for (int k = kbeg; k < kbeg + 128; k++) {
        const float wv = wp[k * 256];
        const float4 ma = *(const float4*)&msm_s[k * 8];
        const float4 mb = *(const float4*)&msm_s[k * 8 + 4];
        acc[0] = fmaf(wv, ma.x, acc[0]); acc[1] = fmaf(wv, ma.y, acc[1]);
        acc[2] = fmaf(wv, ma.z, acc[2]); acc[3] = fmaf(wv, ma.w, acc[3]);
        acc[4] = fmaf(wv, mb.x, acc[4]); acc[5] = fmaf(wv, mb.y, acc[5]);
        acc[6] = fmaf(wv, mb.z, acc[6]); acc[7] = fmaf(wv, mb.w, acc[7]);
    }
    #pragma unroll
    for (int n = 0; n < 8; n++) sacc[(kw * 8 + n) * 32 + fl] = acc[n];
    __syncthreads();

    const int n = tid >> 5;
    float s = 0.f;
    #pragma unroll
    for (int k2 = 0; k2 < 8; k2++) s += sacc[(k2 * 8 + n) * 32 + fl];
    out[(n0 + n) * 256 + f0 + fl] = fmaxf(0.25f * s, 0.f) + bias[f0 + fl];
}

// ---------------- launch ----------------
extern "C" void kernel_launch(void* const* d_in, const int* in_sizes, int n_in,
                              void* d_out, int out_size) {
    (void)in_sizes; (void)n_in; (void)out_size;
    const float* ahs    = (const float*)d_in[0];
    const float* ghs    = (const float*)d_in[1];
    const float* goal   = (const float*)d_in[2];
    const float* action = (const float*)d_in[3];
    const float* Wd     = (const float*)d_in[4];
    const float* bd     = (const float*)d_in[5];
    const float* Wg     = (const float*)d_in[6];
    const float* bg     = (const float*)d_in[7];
    const float* w      = (const float*)d_in[8];
    const float* a      = (const float*)d_in[9];
    const float* bias   = (const float*)d_in[10];
    float* out = (float*)d_out;

    cudaFuncSetAttribute(mainK, cudaFuncAttributeMaxDynamicSharedMemorySize, SM_BYTES);

    prepA<<<NN, 256>>>(ahs, goal, action, Wd, bd);
    prepB<<<128, 256>>>(w, a);
    mainK<<<NN, 256, SM_BYTES>>>(ahs, ghs, Wg, bg);
    projK<<<NN, 256>>>(w, bias, out);
}

// round 6
// speedup vs baseline: 1.8586x; 1.8586x over previous
#include <cuda_runtime.h>
#include <math.h>

#define NN 256
#define HH 256
#define DDE 64
#define NHD 4
#define CHUNK 32
#define NCHUNK 8
#define GH 260     // gh row stride (floats)
#define WGS 264    // Wg_s row stride
#define QSS 68     // qs row stride

typedef unsigned long long ull;

__device__ __forceinline__ ull pk2(float lo, float hi) {
    ull r; asm("mov.b64 %0,{%1,%2};" : "=l"(r) : "f"(lo), "f"(hi)); return r;
}
__device__ __forceinline__ float2 upk2(ull v) {
    float lo, hi; asm("mov.b64 {%0,%1},%2;" : "=f"(lo), "=f"(hi) : "l"(v));
    float2 f; f.x = lo; f.y = hi; return f;
}
__device__ __forceinline__ ull fma2_(ull a, ull b, ull c) {
    ull d; asm("fma.rn.f32x2 %0,%1,%2,%3;" : "=l"(d) : "l"(a), "l"(b), "l"(c)); return d;
}
__device__ __forceinline__ ull mul2_(ull a, ull b) {
    ull d; asm("mul.rn.f32x2 %0,%1,%2;" : "=l"(d) : "l"(a), "l"(b)); return d;
}
__device__ __forceinline__ float tanh_ap(float x) {
    float y; asm("tanh.approx.f32 %0,%1;" : "=f"(y) : "f"(x)); return y;
}
__device__ __forceinline__ float sig_ap(float x) {   // sigmoid via tanh
    return fmaf(tanh_ap(0.5f * x), 0.5f, 0.5f);
}
__device__ __forceinline__ unsigned tf32c(float f) {
    unsigned r; asm("cvt.rna.tf32.f32 %0,%1;" : "=r"(r) : "f"(f)); return r;
}
__device__ __forceinline__ void mma_tf32(float* c, const unsigned* a, const unsigned* b) {
    asm("mma.sync.aligned.m16n8k8.row.col.f32.tf32.tf32.f32 "
        "{%0,%1,%2,%3},{%4,%5,%6,%7},{%8,%9},{%0,%1,%2,%3};"
        : "+f"(c[0]), "+f"(c[1]), "+f"(c[2]), "+f"(c[3])
        : "r"(a[0]), "r"(a[1]), "r"(a[2]), "r"(a[3]), "r"(b[0]), "r"(b[1]));
}

// ---------------- device scratch ----------------
__device__ float g_tTj[NN * HH];   // tanh(ahs[j,h])
__device__ float g_PT[DDE * NN];
__device__ float g_C [NN * DDE];
__device__ float g_u [NHD * HH];
__device__ float g_v [NHD * HH];
__device__ float g_msm[NN * NHD * HH];

// ---------------- prep kernels ----------------
__global__ void prepA(const float* __restrict__ ahs, const float* __restrict__ goal,
                      const float* __restrict__ action, const float* __restrict__ Wd,
                      const float* __restrict__ bd) {
    const int j = blockIdx.x, t = threadIdx.x;
    g_tTj[j * HH + t] = tanhf(ahs[j * HH + t]);
    if (t < DDE) {
        const float a0 = action[j * 2 + 0], a1 = action[j * 2 + 1];
        const float go0 = goal[j * 2 + 0], go1 = goal[j * 2 + 1];
        g_PT[t * NN + j] = a0 * Wd[4 * DDE + t] + a1 * Wd[5 * DDE + t]
                         + go0 * Wd[6 * DDE + t] + go1 * Wd[7 * DDE + t];
        g_C[j * DDE + t] = a0 * Wd[0 * DDE + t] + a1 * Wd[1 * DDE + t]
                         + go0 * Wd[2 * DDE + t] + go1 * Wd[3 * DDE + t] + bd[t];
    }
}

__global__ void prepB(const float* __restrict__ w, const float* __restrict__ a) {
    const int warp = (blockIdx.x * blockDim.x + threadIdx.x) >> 5;  // z*256+h
    const int lane = threadIdx.x & 31;
    const float* row = w + warp * HH;
    float su = 0.f, sv = 0.f;
    #pragma unroll
    for (int f = lane; f < HH; f += 32) {
        const float wv = row[f];
        su = fmaf(wv, a[f], su);
        sv = fmaf(wv, a[HH + f], sv);
    }
    #pragma unroll
    for (int o = 16; o; o >>= 1) {
        su += __shfl_down_sync(0xffffffffu, su, o);
        sv += __shfl_down_sync(0xffffffffu, sv, o);
    }
    if (lane == 0) { g_u[warp] = su; g_v[warp] = sv; }
}

// ---------------- main fused kernel (tensor-core gate GEMM) ----------------
// smem floats: Wg_s 64*264=16896 | gh 32*260=8320 (qs aliased) | spp 1024 |
//              psh 128 | bc 16 | cvec 16  => 26400 floats = 105.6 KB  (2 CTAs/SM)
#define SM_FLOATS (DDE * WGS + CHUNK * GH + 1024 + 128 + 16 + 16)
#define SM_BYTES  (SM_FLOATS * 4)

__global__ void __launch_bounds__(256, 2) mainK(
    const float* __restrict__ ahs, const float* __restrict__ ghs,
    const float* __restrict__ Wg, const float* __restrict__ bg)
{
    extern __shared__ float sm[];
    float* Wg_s = sm;                    // [d][h] stride 264, tf32-converted
    float* gh   = Wg_s + DDE * WGS;      // [jl][h] stride 260
    float* qs   = gh;                    // [jl][d] stride 68 (alias; disjoint lifetime)
    float* spp  = gh + CHUNK * GH;       // [z][jl][w8] = 4*32*8
    float* psh  = spp + 1024;            // [jl][z]
    float* bc   = psh + 128;             // 16
    float* cvec = bc + 16;               // c1[0..3], s0[4..7]

    const int i    = blockIdx.x;
    const int tid  = threadIdx.x;
    const int lane = tid & 31;
    const int warp = tid >> 5;           // warp owns h in [warp*32, warp*32+32)
    const int g    = lane >> 2;          // groupID (row within MMA tile)
    const int T    = lane & 3;           // threadID in group

    // Wg -> smem, tf32-rounded, padded stride
    for (int k = tid; k < DDE * HH; k += 256) {
        const int d = k >> 8, h = k & 255;
        Wg_s[d * WGS + h] = __uint_as_float(tf32c(Wg[k]));
    }

    // prologue dots: warp (z*2 + sel): c1 (u) / s0 (v) for this row
    {
        const int z = warp >> 1;
        const float* src = (warp & 1) ? (g_v + z * HH) : (g_u + z * HH);
        float s = 0.f;
        #pragma unroll
        for (int h = lane; h < HH; h += 32) s = fmaf(ahs[i * HH + h], src[h], s);
        #pragma unroll
        for (int o = 16; o; o >>= 1) s += __shfl_xor_sync(0xffffffffu, s, o);
        if (lane == 0) cvec[(warp & 1) * 4 + z] = s;
    }

    // preload per-thread v pairs (4 heads x 4 ntiles) and gate-bias pairs
    float2 v2[NHD][4], bg2[4];
    #pragma unroll
    for (int nt = 0; nt < 4; nt++) {
        const int hb = warp * 32 + nt * 8 + 2 * T;
        bg2[nt] = *(const float2*)&bg[hb];
        #pragma unroll
        for (int z = 0; z < NHD; z++)
            v2[z][nt] = *(const float2*)&g_v[z * HH + hb];
    }

    const float ahs_i = ahs[i * HH + tid];
    __syncthreads();

    // online-softmax state (replicated across threads)
    float runmax0, runmax1, runmax2, runmax3;
    float denom0 = 1.f, denom1 = 1.f, denom2 = 1.f, denom3 = 1.f;
    {
        const float s0v = cvec[0] + cvec[4], s1v = cvec[1] + cvec[5];
        const float s2v = cvec[2] + cvec[6], s3v = cvec[3] + cvec[7];
        runmax0 = (s0v > 0.f) ? s0v : 0.2f * s0v;
        runmax1 = (s1v > 0.f) ? s1v : 0.2f * s1v;
        runmax2 = (s2v > 0.f) ? s2v : 0.2f * s2v;
        runmax3 = (s3v > 0.f) ? s3v : 0.2f * s3v;
    }
    ull mA = pk2(ahs_i, ahs_i), mB = mA;   // (m0,m1),(m2,m3)

    for (int c = 0; c < NCHUNK; c++) {
        const int j0 = c * CHUNK;

        // qs[jj][d] = tf32(relu(C[i,d] + PT[d, j0+jj]))
        for (int idx = tid; idx < DDE * CHUNK; idx += 256) {
            const int d = idx >> 5, jj = idx & 31;
            const float val = fmaxf(g_C[i * DDE + d] + g_PT[d * NN + j0 + jj], 0.f);
            qs[jj * QSS + d] = __uint_as_float(tf32c(val));
        }
        __syncthreads();

        // ---- tensor-core gate GEMM: 2 Mtiles x 4 ntiles per warp, K=64 ----
        float acc[2][4][4];
        #pragma unroll
        for (int mt = 0; mt < 2; mt++)
            #pragma unroll
            for (int nt = 0; nt < 4; nt++)
                #pragma unroll
                for (int e = 0; e < 4; e++) acc[mt][nt][e] = 0.f;

        #pragma unroll
        for (int kt = 0; kt < 8; kt++) {
            unsigned a[2][4], b[4][2];
            #pragma unroll
            for (int mt = 0; mt < 2; mt++) {
                const int r0 = (mt * 16 + g) * QSS + kt * 8 + T;
                a[mt][0] = __float_as_uint(qs[r0]);
                a[mt][1] = __float_as_uint(qs[r0 + 8 * QSS]);
                a[mt][2] = __float_as_uint(qs[r0 + 4]);
                a[mt][3] = __float_as_uint(qs[r0 + 8 * QSS + 4]);
            }
            #pragma unroll
            for (int nt = 0; nt < 4; nt++) {
                const int bi = (kt * 8 + T) * WGS + warp * 32 + nt * 8 + g;
                b[nt][0] = __float_as_uint(Wg_s[bi]);
                b[nt][1] = __float_as_uint(Wg_s[bi + 4 * WGS]);
            }
            #pragma unroll
            for (int mt = 0; mt < 2; mt++)
                #pragma unroll
                for (int nt = 0; nt < 4; nt++)
                    mma_tf32(acc[mt][nt], a[mt], b[nt]);
        }
        __syncthreads();   // all MMA reads of qs done before gh stores overwrite alias

        // ---- epilogue: bias + sigmoid*tanh (diag override), store gh, scores ----
        float p[4][4];
        #pragma unroll
        for (int r = 0; r < 4; r++)
            #pragma unroll
            for (int z = 0; z < 4; z++) p[r][z] = 0.f;

        #pragma unroll
        for (int mt = 0; mt < 2; mt++) {
            const int ja = j0 + mt * 16 + g;     // row of c0,c1
            const int jb = ja + 8;               // row of c2,c3
            #pragma unroll
            for (int nt = 0; nt < 4; nt++) {
                const int hb = warp * 32 + nt * 8 + 2 * T;
                const float x00 = acc[mt][nt][0] + bg2[nt].x;
                const float x01 = acc[mt][nt][1] + bg2[nt].y;
                const float x10 = acc[mt][nt][2] + bg2[nt].x;
                const float x11 = acc[mt][nt][3] + bg2[nt].y;
                float2 gva, gvb;
                if (ja == i) {
                    gva = *(const float2*)&ghs[i * HH + hb];
                } else {
                    const float2 t = *(const float2*)&g_tTj[ja * HH + hb];
                    gva.x = sig_ap(x00) * t.x;
                    gva.y = sig_ap(x01) * t.y;
                }
                if (jb == i) {
                    gvb = *(const float2*)&ghs[i * HH + hb];
                } else {
                    const float2 t = *(const float2*)&g_tTj[jb * HH + hb];
                    gvb.x = sig_ap(x10) * t.x;
                    gvb.y = sig_ap(x11) * t.y;
                }
                *(float2*)&gh[(mt * 16 + g) * GH + hb]     = gva;
                *(float2*)&gh[(mt * 16 + g + 8) * GH + hb] = gvb;
                #pragma unroll
                for (int z = 0; z < 4; z++) {
                    p[mt * 2 + 0][z] = fmaf(gva.x, v2[z][nt].x,
                                       fmaf(gva.y, v2[z][nt].y, p[mt * 2 + 0][z]));
                    p[mt * 2 + 1][z] = fmaf(gvb.x, v2[z][nt].x,
                                       fmaf(gvb.y, v2[z][nt].y, p[mt * 2 + 1][z]));
                }
            }
        }
        // quad-reduce (h-slice within warp) and stash per-warp partials
        #pragma unroll
        for (int r = 0; r < 4; r++)
            #pragma unroll
            for (int z = 0; z < 4; z++) {
                p[r][z] += __shfl_xor_sync(0xffffffffu, p[r][z], 1);
                p[r][z] += __shfl_xor_sync(0xffffffffu, p[r][z], 2);
            }
        #pragma unroll
        for (int r = 0; r < 4; r++)
            spp[T * 256 + (r * 8 + g) * 8 + warp] = p[r][T];
        __syncthreads();

        // ---- chunk softmax: warp z in {0..3} ----
        if (warp < 4) {
            float e = cvec[warp];
            #pragma unroll
            for (int w8 = 0; w8 < 8; w8++) e += spp[warp * 256 + lane * 8 + w8];
            e = (e > 0.f) ? e : 0.2f * e;
            const float rmz = (warp == 0) ? runmax0 : (warp == 1) ? runmax1
                            : (warp == 2) ? runmax2 : runmax3;
            float mx = e;
            #pragma unroll
            for (int o = 16; o; o >>= 1) mx = fmaxf(mx, __shfl_xor_sync(0xffffffffu, mx, o));
            const float nm = fmaxf(rmz, mx);
            const float pp = __expf(e - nm);
            psh[lane * 4 + warp] = pp;
            float ps = pp;
            #pragma unroll
            for (int o = 16; o; o >>= 1) ps += __shfl_xor_sync(0xffffffffu, ps, o);
            if (lane == 0) { bc[warp] = mx; bc[4 + warp] = ps; }
        }
        __syncthreads();

        // ---- merge running state, accumulate m for h = tid ----
        {
            const float nm0 = fmaxf(runmax0, bc[0]);
            const float nm1 = fmaxf(runmax1, bc[1]);
            const float nm2 = fmaxf(runmax2, bc[2]);
            const float nm3 = fmaxf(runmax3, bc[3]);
            const float s0 = __expf(runmax0 - nm0), s1 = __expf(runmax1 - nm1);
            const float s2 = __expf(runmax2 - nm2), s3 = __expf(runmax3 - nm3);
            denom0 = denom0 * s0 + bc[4]; denom1 = denom1 * s1 + bc[5];
            denom2 = denom2 * s2 + bc[6]; denom3 = denom3 * s3 + bc[7];
            runmax0 = nm0; runmax1 = nm1; runmax2 = nm2; runmax3 = nm3;
            mA = mul2_(mA, pk2(s0, s1));
            mB = mul2_(mB, pk2(s2, s3));
        }
        #pragma unroll 4
        for (int jj = 0; jj < CHUNK; jj++) {
            const float ghv = gh[jj * GH + tid];
            const ulonglong2 pp = *(const ulonglong2*)&psh[jj * 4];
            const ull gd = pk2(ghv, ghv);
            mA = fma2_(pp.x, gd, mA);
            mB = fma2_(pp.y, gd, mB);
        }
        __syncthreads();   // gh (alias qs) safe to overwrite next chunk
    }

    // write normalized m: g_msm[i][z*256 + h]
    {
        const float2 fA = upk2(mA), fB = upk2(mB);
        g_msm[i * (NHD * HH) + 0 * HH + tid] = fA.x / denom0;
        g_msm[i * (NHD * HH) + 1 * HH + tid] = fA.y / denom1;
        g_msm[i * (NHD * HH) + 2 * HH + tid] = fB.x / denom2;
        g_msm[i * (NHD * HH) + 3 * HH + tid] = fB.y / denom3;
    }
}

// ---------------- projection kernel (scalar, deeper unroll) ----------------
__global__ void __launch_bounds__(256) projK(const float* __restrict__ w,
                                             const float* __restrict__ bias,
                                             float* __restrict__ out) {
    __shared__ float msm_s[8192];   // [k][n], n contiguous (8)
    __shared__ float sacc[2048];    // [kw][n][fl]
    const int tid = threadIdx.x;
    const int f0 = (blockIdx.x & 7) * 32;
    const int n0 = (blockIdx.x >> 3) * 8;

    for (int idx = tid; idx < 8192; idx += 256) {
        const int k = idx >> 3, n = idx & 7;
        msm_s[idx] = g_msm[(n0 + n) * 1024 + k];
    }
    __syncthreads();

    const int fl = tid & 31, kw = tid >> 5;
    float acc[8] = {0.f, 0.f, 0.f, 0.f, 0.f, 0.f, 0.f, 0.f};
    const float* wp = w + f0 + fl;
    const int kbeg = kw * 128;
    #pragma unroll 8
    for (int k = kbeg; k < kbeg + 128; k++) {
        const float wv = wp[k * 256];
        const float4 ma = *(const float4*)&msm_s[k * 8];
        const float4 mb = *(const float4*)&msm_s[k * 8 + 4];
        acc[0] = fmaf(wv, ma.x, acc[0]); acc[1] = fmaf(wv, ma.y, acc[1]);
        acc[2] = fmaf(wv, ma.z, acc[2]); acc[3] = fmaf(wv, ma.w, acc[3]);
        acc[4] = fmaf(wv, mb.x, acc[4]); acc[5] = fmaf(wv, mb.y, acc[5]);
        acc[6] = fmaf(wv, mb.z, acc[6]); acc[7] = fmaf(wv, mb.w, acc[7]);
    }
    #pragma unroll
    for (int n = 0; n < 8; n++) sacc[(kw * 8 + n) * 32 + fl] = acc[n];
    __syncthreads();

    const int n = tid >> 5;
    float s = 0.f;
    #pragma unroll
    for (int k2 = 0; k2 < 8; k2++) s += sacc[(k2 * 8 + n) * 32 + fl];
    out[(n0 + n) * 256 + f0 + fl] = fmaxf(0.25f * s, 0.f) + bias[f0 + fl];
}

// ---------------- launch ----------------
extern "C" void kernel_launch(void* const* d_in, const int* in_sizes, int n_in,
                              void* d_out, int out_size) {
    (void)in_sizes; (void)n_in; (void)out_size;
    const float* ahs    = (const float*)d_in[0];
    const float* ghs    = (const float*)d_in[1];
    const float* goal   = (const float*)d_in[2];
    const float* action = (const float*)d_in[3];
    const float* Wd     = (const float*)d_in[4];
    const float* bd     = (const float*)d_in[5];
    const float* Wg     = (const float*)d_in[6];
    const float* bg     = (const float*)d_in[7];
    const float* w      = (const float*)d_in[8];
    const float* a      = (const float*)d_in[9];
    const float* bias   = (const float*)d_in[10];
    float* out = (float*)d_out;

    cudaFuncSetAttribute(mainK, cudaFuncAttributeMaxDynamicSharedMemorySize, SM_BYTES);

    prepA<<<NN, 256>>>(ahs, goal, action, Wd, bd);
    prepB<<<128, 256>>>(w, a);
    mainK<<<NN, 256, SM_BYTES>>>(ahs, ghs, Wg, bg);
    projK<<<NN, 256>>>(w, bias, out);
}

// round 7
// speedup vs baseline: 1.8911x; 1.0175x over previous
#include <cuda_runtime.h>
#include <math.h>

#define NN 256
#define HH 256
#define DDE 64
#define NHD 4
#define CHUNK 32
#define NCHUNK 8
#define GH 260     // gh row stride (floats)
#define WGS 264    // Wg_s row stride
#define QSS 68     // qs row stride

typedef unsigned long long ull;

__device__ __forceinline__ ull pk2(float lo, float hi) {
    ull r; asm("mov.b64 %0,{%1,%2};" : "=l"(r) : "f"(lo), "f"(hi)); return r;
}
__device__ __forceinline__ float2 upk2(ull v) {
    float lo, hi; asm("mov.b64 {%0,%1},%2;" : "=f"(lo), "=f"(hi) : "l"(v));
    float2 f; f.x = lo; f.y = hi; return f;
}
__device__ __forceinline__ ull fma2_(ull a, ull b, ull c) {
    ull d; asm("fma.rn.f32x2 %0,%1,%2,%3;" : "=l"(d) : "l"(a), "l"(b), "l"(c)); return d;
}
__device__ __forceinline__ ull mul2_(ull a, ull b) {
    ull d; asm("mul.rn.f32x2 %0,%1,%2;" : "=l"(d) : "l"(a), "l"(b)); return d;
}
__device__ __forceinline__ float tanh_ap(float x) {
    float y; asm("tanh.approx.f32 %0,%1;" : "=f"(y) : "f"(x)); return y;
}
__device__ __forceinline__ float sig_ap(float x) {   // sigmoid via tanh
    return fmaf(tanh_ap(0.5f * x), 0.5f, 0.5f);
}
__device__ __forceinline__ unsigned tf32c(float f) {
    unsigned r; asm("cvt.rna.tf32.f32 %0,%1;" : "=r"(r) : "f"(f)); return r;
}
__device__ __forceinline__ void mma_tf32(float* c, const unsigned* a, const unsigned* b) {
    asm("mma.sync.aligned.m16n8k8.row.col.f32.tf32.tf32.f32 "
        "{%0,%1,%2,%3},{%4,%5,%6,%7},{%8,%9},{%0,%1,%2,%3};"
        : "+f"(c[0]), "+f"(c[1]), "+f"(c[2]), "+f"(c[3])
        : "r"(a[0]), "r"(a[1]), "r"(a[2]), "r"(a[3]), "r"(b[0]), "r"(b[1]));
}

// ---------------- device scratch ----------------
__device__ float g_tTj[NN * HH];   // tanh(ahs[j,h])
__device__ float g_PT[DDE * NN];
__device__ float g_C [NN * DDE];
__device__ float g_u [NHD * HH];
__device__ float g_v [NHD * HH];
__device__ float g_msm[NN * NHD * HH];

// ---------------- merged prep kernel ----------------
// blocks 0..255: prepA work for row j = blockIdx
// blocks 256..383: prepB work, warp id = (blockIdx-256)*8 + local warp
__global__ void prepK(const float* __restrict__ ahs, const float* __restrict__ goal,
                      const float* __restrict__ action, const float* __restrict__ Wd,
                      const float* __restrict__ bd, const float* __restrict__ w,
                      const float* __restrict__ a) {
    const int bx = blockIdx.x, t = threadIdx.x;
    if (bx < NN) {
        const int j = bx;
        g_tTj[j * HH + t] = tanhf(ahs[j * HH + t]);
        if (t < DDE) {
            const float a0 = action[j * 2 + 0], a1 = action[j * 2 + 1];
            const float go0 = goal[j * 2 + 0], go1 = goal[j * 2 + 1];
            g_PT[t * NN + j] = a0 * Wd[4 * DDE + t] + a1 * Wd[5 * DDE + t]
                             + go0 * Wd[6 * DDE + t] + go1 * Wd[7 * DDE + t];
            g_C[j * DDE + t] = a0 * Wd[0 * DDE + t] + a1 * Wd[1 * DDE + t]
                             + go0 * Wd[2 * DDE + t] + go1 * Wd[3 * DDE + t] + bd[t];
        }
    } else {
        const int warp = (bx - NN) * 8 + (t >> 5);  // 0..1023 = z*256+h
        const int lane = t & 31;
        const float* row = w + warp * HH;
        float su = 0.f, sv = 0.f;
        #pragma unroll
        for (int f = lane; f < HH; f += 32) {
            const float wv = row[f];
            su = fmaf(wv, a[f], su);
            sv = fmaf(wv, a[HH + f], sv);
        }
        #pragma unroll
        for (int o = 16; o; o >>= 1) {
            su += __shfl_down_sync(0xffffffffu, su, o);
            sv += __shfl_down_sync(0xffffffffu, sv, o);
        }
        if (lane == 0) { g_u[warp] = su; g_v[warp] = sv; }
    }
}

// ---------------- main fused kernel (tensor-core gate GEMM) ----------------
// smem floats: Wg_s 64*264=16896 | gh 32*260=8320 (qs aliased) | spp 1024 |
//              psh 128 | bc 16 | cvec 16  => 26400 floats = 105.6 KB  (2 CTAs/SM)
#define SM_FLOATS (DDE * WGS + CHUNK * GH + 1024 + 128 + 16 + 16)
#define SM_BYTES  (SM_FLOATS * 4)

__global__ void __launch_bounds__(256, 2) mainK(
    const float* __restrict__ ahs, const float* __restrict__ ghs,
    const float* __restrict__ Wg, const float* __restrict__ bg)
{
    extern __shared__ float sm[];
    float* Wg_s = sm;                    // [d][h] stride 264, tf32-converted
    float* gh   = Wg_s + DDE * WGS;      // [jl][h] stride 260
    float* qs   = gh;                    // [jl][d] stride 68 (alias; disjoint lifetime)
    float* spp  = gh + CHUNK * GH;       // [z][jl][w8] = 4*32*8
    float* psh  = spp + 1024;            // [jl][z]
    float* bc   = psh + 128;             // 16
    float* cvec = bc + 16;               // c1[0..3], s0[4..7]

    const int i    = blockIdx.x;
    const int tid  = threadIdx.x;
    const int lane = tid & 31;
    const int warp = tid >> 5;           // warp owns h in [warp*32, warp*32+32)
    const int g    = lane >> 2;          // groupID (row within MMA tile)
    const int T    = lane & 3;           // threadID in group

    // Wg -> smem, tf32-rounded, padded stride
    for (int k = tid; k < DDE * HH; k += 256) {
        const int d = k >> 8, h = k & 255;
        Wg_s[d * WGS + h] = __uint_as_float(tf32c(Wg[k]));
    }

    // prologue dots: warp (z*2 + sel): c1 (u) / s0 (v) for this row
    {
        const int z = warp >> 1;
        const float* src = (warp & 1) ? (g_v + z * HH) : (g_u + z * HH);
        float s = 0.f;
        #pragma unroll
        for (int h = lane; h < HH; h += 32) s = fmaf(ahs[i * HH + h], src[h], s);
        #pragma unroll
        for (int o = 16; o; o >>= 1) s += __shfl_xor_sync(0xffffffffu, s, o);
        if (lane == 0) cvec[(warp & 1) * 4 + z] = s;
    }

    // preload per-thread v pairs (4 heads x 4 ntiles) and gate-bias pairs
    float2 v2[NHD][4], bg2[4];
    #pragma unroll
    for (int nt = 0; nt < 4; nt++) {
        const int hb = warp * 32 + nt * 8 + 2 * T;
        bg2[nt] = *(const float2*)&bg[hb];
        #pragma unroll
        for (int z = 0; z < NHD; z++)
            v2[z][nt] = *(const float2*)&g_v[z * HH + hb];
    }

    const float ahs_i = ahs[i * HH + tid];
    __syncthreads();

    // online-softmax state (replicated across threads)
    float runmax0, runmax1, runmax2, runmax3;
    float denom0 = 1.f, denom1 = 1.f, denom2 = 1.f, denom3 = 1.f;
    {
        const float s0v = cvec[0] + cvec[4], s1v = cvec[1] + cvec[5];
        const float s2v = cvec[2] + cvec[6], s3v = cvec[3] + cvec[7];
        runmax0 = (s0v > 0.f) ? s0v : 0.2f * s0v;
        runmax1 = (s1v > 0.f) ? s1v : 0.2f * s1v;
        runmax2 = (s2v > 0.f) ? s2v : 0.2f * s2v;
        runmax3 = (s3v > 0.f) ? s3v : 0.2f * s3v;
    }
    ull mA = pk2(ahs_i, ahs_i), mB = mA;   // (m0,m1),(m2,m3)

    for (int c = 0; c < NCHUNK; c++) {
        const int j0 = c * CHUNK;

        // qs[jj][d] = tf32(relu(C[i,d] + PT[d, j0+jj]))
        for (int idx = tid; idx < DDE * CHUNK; idx += 256) {
            const int d = idx >> 5, jj = idx & 31;
            const float val = fmaxf(g_C[i * DDE + d] + g_PT[d * NN + j0 + jj], 0.f);
            qs[jj * QSS + d] = __uint_as_float(tf32c(val));
        }
        __syncthreads();

        // ---- tensor-core gate GEMM: 2 Mtiles x 4 ntiles per warp, K=64 ----
        float acc[2][4][4];
        #pragma unroll
        for (int mt = 0; mt < 2; mt++)
            #pragma unroll
            for (int nt = 0; nt < 4; nt++)
                #pragma unroll
                for (int e = 0; e < 4; e++) acc[mt][nt][e] = 0.f;

        #pragma unroll
        for (int kt = 0; kt < 8; kt++) {
            unsigned a[2][4], b[4][2];
            #pragma unroll
            for (int mt = 0; mt < 2; mt++) {
                const int r0 = (mt * 16 + g) * QSS + kt * 8 + T;
                a[mt][0] = __float_as_uint(qs[r0]);
                a[mt][1] = __float_as_uint(qs[r0 + 8 * QSS]);
                a[mt][2] = __float_as_uint(qs[r0 + 4]);
                a[mt][3] = __float_as_uint(qs[r0 + 8 * QSS + 4]);
            }
            #pragma unroll
            for (int nt = 0; nt < 4; nt++) {
                const int bi = (kt * 8 + T) * WGS + warp * 32 + nt * 8 + g;
                b[nt][0] = __float_as_uint(Wg_s[bi]);
                b[nt][1] = __float_as_uint(Wg_s[bi + 4 * WGS]);
            }
            #pragma unroll
            for (int mt = 0; mt < 2; mt++)
                #pragma unroll
                for (int nt = 0; nt < 4; nt++)
                    mma_tf32(acc[mt][nt], a[mt], b[nt]);
        }
        __syncthreads();   // all MMA reads of qs done before gh stores overwrite alias

        // ---- epilogue: bias + sigmoid*tanh (diag override), store gh, scores ----
        float p[4][4];
        #pragma unroll
        for (int r = 0; r < 4; r++)
            #pragma unroll
            for (int z = 0; z < 4; z++) p[r][z] = 0.f;

        #pragma unroll
        for (int mt = 0; mt < 2; mt++) {
            const int ja = j0 + mt * 16 + g;     // row of c0,c1
            const int jb = ja + 8;               // row of c2,c3
            #pragma unroll
            for (int nt = 0; nt < 4; nt++) {
                const int hb = warp * 32 + nt * 8 + 2 * T;
                const float x00 = acc[mt][nt][0] + bg2[nt].x;
                const float x01 = acc[mt][nt][1] + bg2[nt].y;
                const float x10 = acc[mt][nt][2] + bg2[nt].x;
                const float x11 = acc[mt][nt][3] + bg2[nt].y;
                float2 gva, gvb;
                if (ja == i) {
                    gva = *(const float2*)&ghs[i * HH + hb];
                } else {
                    const float2 t = *(const float2*)&g_tTj[ja * HH + hb];
                    gva.x = sig_ap(x00) * t.x;
                    gva.y = sig_ap(x01) * t.y;
                }
                if (jb == i) {
                    gvb = *(const float2*)&ghs[i * HH + hb];
                } else {
                    const float2 t = *(const float2*)&g_tTj[jb * HH + hb];
                    gvb.x = sig_ap(x10) * t.x;
                    gvb.y = sig_ap(x11) * t.y;
                }
                *(float2*)&gh[(mt * 16 + g) * GH + hb]     = gva;
                *(float2*)&gh[(mt * 16 + g + 8) * GH + hb] = gvb;
                #pragma unroll
                for (int z = 0; z < 4; z++) {
                    p[mt * 2 + 0][z] = fmaf(gva.x, v2[z][nt].x,
                                       fmaf(gva.y, v2[z][nt].y, p[mt * 2 + 0][z]));
                    p[mt * 2 + 1][z] = fmaf(gvb.x, v2[z][nt].x,
                                       fmaf(gvb.y, v2[z][nt].y, p[mt * 2 + 1][z]));
                }
            }
        }
        // quad-reduce (h-slice within warp) and stash per-warp partials
        #pragma unroll
        for (int r = 0; r < 4; r++)
            #pragma unroll
            for (int z = 0; z < 4; z++) {
                p[r][z] += __shfl_xor_sync(0xffffffffu, p[r][z], 1);
                p[r][z] += __shfl_xor_sync(0xffffffffu, p[r][z], 2);
            }
        #pragma unroll
        for (int r = 0; r < 4; r++)
            spp[T * 256 + (r * 8 + g) * 8 + warp] = p[r][T];
        __syncthreads();

        // ---- chunk softmax: warp z in {0..3} ----
        if (warp < 4) {
            float e = cvec[warp];
            #pragma unroll
            for (int w8 = 0; w8 < 8; w8++) e += spp[warp * 256 + lane * 8 + w8];
            e = (e > 0.f) ? e : 0.2f * e;
            const float rmz = (warp == 0) ? runmax0 : (warp == 1) ? runmax1
                            : (warp == 2) ? runmax2 : runmax3;
            float mx = e;
            #pragma unroll
            for (int o = 16; o; o >>= 1) mx = fmaxf(mx, __shfl_xor_sync(0xffffffffu, mx, o));
            const float nm = fmaxf(rmz, mx);
            const float pp = __expf(e - nm);
            psh[lane * 4 + warp] = pp;
            float ps = pp;
            #pragma unroll
            for (int o = 16; o; o >>= 1) ps += __shfl_xor_sync(0xffffffffu, ps, o);
            if (lane == 0) { bc[warp] = mx; bc[4 + warp] = ps; }
        }
        __syncthreads();

        // ---- merge running state, accumulate m for h = tid ----
        {
            const float nm0 = fmaxf(runmax0, bc[0]);
            const float nm1 = fmaxf(runmax1, bc[1]);
            const float nm2 = fmaxf(runmax2, bc[2]);
            const float nm3 = fmaxf(runmax3, bc[3]);
            const float s0 = __expf(runmax0 - nm0), s1 = __expf(runmax1 - nm1);
            const float s2 = __expf(runmax2 - nm2), s3 = __expf(runmax3 - nm3);
            denom0 = denom0 * s0 + bc[4]; denom1 = denom1 * s1 + bc[5];
            denom2 = denom2 * s2 + bc[6]; denom3 = denom3 * s3 + bc[7];
            runmax0 = nm0; runmax1 = nm1; runmax2 = nm2; runmax3 = nm3;
            mA = mul2_(mA, pk2(s0, s1));
            mB = mul2_(mB, pk2(s2, s3));
        }
        #pragma unroll 4
        for (int jj = 0; jj < CHUNK; jj++) {
            const float ghv = gh[jj * GH + tid];
            const ulonglong2 pp = *(const ulonglong2*)&psh[jj * 4];
            const ull gd = pk2(ghv, ghv);
            mA = fma2_(pp.x, gd, mA);
            mB = fma2_(pp.y, gd, mB);
        }
        __syncthreads();   // gh (alias qs) safe to overwrite next chunk
    }

    // write normalized m: g_msm[i][z*256 + h]
    {
        const float2 fA = upk2(mA), fB = upk2(mB);
        g_msm[i * (NHD * HH) + 0 * HH + tid] = fA.x / denom0;
        g_msm[i * (NHD * HH) + 1 * HH + tid] = fA.y / denom1;
        g_msm[i * (NHD * HH) + 2 * HH + tid] = fB.x / denom2;
        g_msm[i * (NHD * HH) + 3 * HH + tid] = fB.y / denom3;
    }
}

// ---------------- projection kernel: 512 threads, k-split 16 ----------------
__global__ void __launch_bounds__(512) projK(const float* __restrict__ w,
                                             const float* __restrict__ bias,
                                             float* __restrict__ out) {
    __shared__ float msm_s[8192];   // [k][n], n contiguous (8)
    __shared__ float sacc[4096];    // [kw(16)][n(8)][fl(32)]
    const int tid = threadIdx.x;
    const int f0 = (blockIdx.x & 7) * 32;
    const int n0 = (blockIdx.x >> 3) * 8;

    for (int idx = tid; idx < 8192; idx += 512) {
        const int k = idx >> 3, n = idx & 7;
        msm_s[idx] = g_msm[(n0 + n) * 1024 + k];
    }
    __syncthreads();

    const int fl = tid & 31, kw = tid >> 5;   // kw 0..15
    float acc[8] = {0.f, 0.f, 0.f, 0.f, 0.f, 0.f, 0.f, 0.f};
    const float* wp = w + f0 + fl;
    const int kbeg = kw * 64;
    #pragma unroll 8
    for (int k = kbeg; k < kbeg + 64; k++) {
        const float wv = wp[k * 256];
        const float4 ma = *(const float4*)&msm_s[k * 8];
        const float4 mb = *(const float4*)&msm_s[k * 8 + 4];
        acc[0] = fmaf(wv, ma.x, acc[0]); acc[1] = fmaf(wv, ma.y, acc[1]);
        acc[2] = fmaf(wv, ma.z, acc[2]); acc[3] = fmaf(wv, ma.w, acc[3]);
        acc[4] = fmaf(wv, mb.x, acc[4]); acc[5] = fmaf(wv, mb.y, acc[5]);
        acc[6] = fmaf(wv, mb.z, acc[6]); acc[7] = fmaf(wv, mb.w, acc[7]);
    }
    #pragma unroll
    for (int n = 0; n < 8; n++) sacc[(kw * 8 + n) * 32 + fl] = acc[n];
    __syncthreads();

    if (tid < 256) {
        const int n = tid >> 5;
        float s = 0.f;
        #pragma unroll
        for (int k2 = 0; k2 < 16; k2++) s += sacc[(k2 * 8 + n) * 32 + fl];
        out[(n0 + n) * 256 + f0 + fl] = fmaxf(0.25f * s, 0.f) + bias[f0 + fl];
    }
}

// ---------------- launch ----------------
extern "C" void kernel_launch(void* const* d_in, const int* in_sizes, int n_in,
                              void* d_out, int out_size) {
    (void)in_sizes; (void)n_in; (void)out_size;
    const float* ahs    = (const float*)d_in[0];
    const float* ghs    = (const float*)d_in[1];
    const float* goal   = (const float*)d_in[2];
    const float* action = (const float*)d_in[3];
    const float* Wd     = (const float*)d_in[4];
    const float* bd     = (const float*)d_in[5];
    const float* Wg     = (const float*)d_in[6];
    const float* bg     = (const float*)d_in[7];
    const float* w      = (const float*)d_in[8];
    const float* a      = (const float*)d_in[9];
    const float* bias   = (const float*)d_in[10];
    float* out = (float*)d_out;

    cudaFuncSetAttribute(mainK, cudaFuncAttributeMaxDynamicSharedMemorySize, SM_BYTES);

    prepK<<<NN + 128, 256>>>(ahs, goal, action, Wd, bd, w, a);
    mainK<<<NN, 256, SM_BYTES>>>(ahs, ghs, Wg, bg);
    projK<<<NN, 512>>>(w, bias, out);
}